// round 1
// baseline (speedup 1.0000x reference)
#include <cuda_runtime.h>

// LQR via Riccati recursion instead of dense 5120x5120 KKT solve.
// T=128, n_state=16, n_ctrl=8, n_all=24.

constexpr int TT = 128;
constexpr int NS = 16;
constexpr int NC = 8;
constexpr int NA = 24;   // NS + NC
constexpr int NTHR = NA * NA;  // 576

// Per-stage gains/value-function storage (written in backward pass, read in forward pass)
__device__ float g_K[TT][NC][NS];
__device__ float g_kk[TT][NC];
__device__ float g_P[TT][NS][NS];
__device__ float g_p[TT][NS];

__global__ void __launch_bounds__(NTHR, 1) lqr_riccati_kernel(
    const float* __restrict__ A,    // [NS, NS]
    const float* __restrict__ B,    // [NS, NC]
    const float* __restrict__ x0,   // [NS]
    const float* __restrict__ C,    // [TT, NA, NA]
    const float* __restrict__ c,    // [TT, NA]
    float* __restrict__ out)        // [TT*NA + TT*NS]  (z then mu)
{
    __shared__ float sF[NS][NA];    // [A B]
    __shared__ float sP[NS][NS];
    __shared__ float sp[NS];
    __shared__ float sW[NS][NA];    // P * F
    __shared__ float sQ[NA][NA];
    __shared__ float sq[NA];
    __shared__ float sL[NC][NC];    // Cholesky factor of Quu (lower)
    __shared__ float sK[NC][NS];
    __shared__ float skk[NC];
    __shared__ float sx[2][NS];
    __shared__ float su[NC];

    const int tid = threadIdx.x;

    // Load F = [A B] into shared
    if (tid < NS * NA) {
        int i = tid / NA, j = tid % NA;
        sF[i][j] = (j < NS) ? A[i * NS + j] : B[i * NC + (j - NS)];
    }

    // Prefetch C_{T-1}, c_{T-1} into registers
    float creg = C[(TT - 1) * NA * NA + tid];
    float cqreg = (tid < NA) ? c[(TT - 1) * NA + tid] : 0.0f;
    __syncthreads();

    // ---------------- Backward Riccati pass ----------------
    for (int t = TT - 1; t >= 0; --t) {
        // Phase A: W = P_{t+1} * F   (skip on last stage)
        if (t < TT - 1) {
            if (tid < NS * NA) {
                int i = tid / NA, j = tid % NA;
                float s = 0.0f;
#pragma unroll
                for (int k = 0; k < NS; ++k) s += sP[i][k] * sF[k][j];
                sW[i][j] = s;
            }
            __syncthreads();
        }

        // Phase B: Q = C_t + F^T W ; q = c_t + F^T p
        {
            int i = tid / NA, j = tid % NA;
            float s = creg;
            if (t < TT - 1) {
#pragma unroll
                for (int k = 0; k < NS; ++k) s += sF[k][i] * sW[k][j];
            }
            sQ[i][j] = s;
        }
        if (tid < NA) {
            float s = cqreg;
            if (t < TT - 1) {
#pragma unroll
                for (int k = 0; k < NS; ++k) s += sF[k][tid] * sp[k];
            }
            sq[tid] = s;
        }
        __syncthreads();

        // Prefetch next stage's C tile (consumed next iteration's Phase B,
        // hidden behind Cholesky / solves / P update below)
        if (t > 0) {
            creg = C[(t - 1) * NA * NA + tid];
            if (tid < NA) cqreg = c[(t - 1) * NA + tid];
        }

        // Phase C: Cholesky of Quu (8x8) — single thread, fully unrolled
        if (tid == 0) {
#pragma unroll
            for (int i = 0; i < NC; ++i) {
#pragma unroll
                for (int j = 0; j <= i; ++j) {
                    float s = sQ[NS + i][NS + j];
#pragma unroll
                    for (int k = 0; k < NC; ++k)
                        if (k < j) s -= sL[i][k] * sL[j][k];
                    if (i == j) sL[i][j] = sqrtf(s);
                    else        sL[i][j] = s / sL[j][j];
                }
            }
        }
        __syncthreads();

        // Phase D: solve Quu * [K | kk] = [Qux | qu]  (17 RHS in parallel)
        if (tid < NS + 1) {
            float y[NC];
#pragma unroll
            for (int a = 0; a < NC; ++a)
                y[a] = (tid < NS) ? sQ[NS + a][tid] : sq[NS + a];
            // forward substitution L y' = y
#pragma unroll
            for (int a = 0; a < NC; ++a) {
                float s = y[a];
#pragma unroll
                for (int k = 0; k < NC; ++k)
                    if (k < a) s -= sL[a][k] * y[k];
                y[a] = s / sL[a][a];
            }
            // back substitution L^T y'' = y'
#pragma unroll
            for (int a = NC - 1; a >= 0; --a) {
                float s = y[a];
#pragma unroll
                for (int k = 0; k < NC; ++k)
                    if (k > a) s -= sL[k][a] * y[k];
                y[a] = s / sL[a][a];
            }
            if (tid < NS) {
#pragma unroll
                for (int a = 0; a < NC; ++a) {
                    sK[a][tid] = y[a];
                    g_K[t][a][tid] = y[a];
                }
            } else {
#pragma unroll
                for (int a = 0; a < NC; ++a) {
                    skk[a] = y[a];
                    g_kk[t][a] = y[a];
                }
            }
        }
        __syncthreads();

        // Phase E: P = Qxx - Qxu K ; p = qx - Qxu kk
        if (tid < NS * NS) {
            int i = tid / NS, j = tid % NS;
            float s = sQ[i][j];
#pragma unroll
            for (int m = 0; m < NC; ++m) s -= sQ[i][NS + m] * sK[m][j];
            sP[i][j] = s;
            g_P[t][i][j] = s;
        }
        if (tid < NS) {
            float s = sq[tid];
#pragma unroll
            for (int m = 0; m < NC; ++m) s -= sQ[tid][NS + m] * skk[m];
            sp[tid] = s;
            g_p[t][tid] = s;
        }
        __syncthreads();
    }

    // ---------------- Forward rollout ----------------
    if (tid < NS) sx[0][tid] = x0[tid];
    __syncthreads();

    for (int t = 0; t < TT; ++t) {
        const int cur = t & 1;
        // warp 0: u_t = -(K_t x_t + kk_t)
        if (tid < NC) {
            float s = g_kk[t][tid];
#pragma unroll
            for (int k = 0; k < NS; ++k) s += g_K[t][tid][k] * sx[cur][k];
            su[tid] = -s;
            out[t * NA + NS + tid] = -s;
        }
        // warp 1: mu_t = P_t x_t + p_t  (negated at t=0)
        if (tid >= 32 && tid < 32 + NS) {
            int i = tid - 32;
            float s = g_p[t][i];
#pragma unroll
            for (int k = 0; k < NS; ++k) s += g_P[t][i][k] * sx[cur][k];
            out[TT * NA + t * NS + i] = (t == 0) ? -s : s;
        }
        // warp 2: write x part of z
        if (tid >= 64 && tid < 64 + NS) {
            int i = tid - 64;
            out[t * NA + i] = sx[cur][i];
        }
        __syncthreads();
        // x_{t+1} = A x_t + B u_t
        if (tid < NS && t < TT - 1) {
            float s = 0.0f;
#pragma unroll
            for (int k = 0; k < NS; ++k) s += sF[tid][k] * sx[cur][k];
#pragma unroll
            for (int k = 0; k < NC; ++k) s += sF[tid][NS + k] * su[k];
            sx[1 - cur][tid] = s;
        }
        __syncthreads();
    }
}

extern "C" void kernel_launch(void* const* d_in, const int* in_sizes, int n_in,
                              void* d_out, int out_size) {
    const float* A  = (const float*)d_in[0];
    const float* B  = (const float*)d_in[1];
    const float* x0 = (const float*)d_in[2];
    const float* C  = (const float*)d_in[3];
    const float* c  = (const float*)d_in[4];
    float* out = (float*)d_out;
    lqr_riccati_kernel<<<1, NTHR>>>(A, B, x0, C, c, out);
}

// round 2
// speedup vs baseline: 3.6313x; 3.6313x over previous
#include <cuda_runtime.h>

// LQR via Riccati recursion. T=128, n_state=16, n_ctrl=8, n_all=24.
// Single CTA, 160 threads, latency-optimized:
//  - float4-vectorized shared-memory GEMM phases, F cached in registers
//  - per-thread redundant register Cholesky (rsqrtf, no divides, no broadcast)
//  - closed-loop matrix Acl = A - B K precomputed -> single-warp shuffle rollout
//  - u / mu outputs computed in one parallel post-pass

constexpr int TT = 128, NS = 16, NC = 8, NA = 24;
constexpr int NTHR = 160;

constexpr int QS = 28;  // sQ row stride (floats), 112B: 16B-aligned, conflict-poor
constexpr int WS = 28;  // sW row stride
constexpr int PS = 20;  // sP row stride, 80B aligned
constexpr int AS = 17;  // Acl row stride (scalar access, conflict-free)

__device__ __align__(16) float g_K[TT][NC][NS];
__device__ float g_kk[TT][NC];
__device__ __align__(16) float g_P[TT][NS][NS];
__device__ float g_p[TT][NS];

__global__ void __launch_bounds__(NTHR, 1) lqr_kernel(
    const float* __restrict__ A, const float* __restrict__ B,
    const float* __restrict__ x0, const float* __restrict__ C,
    const float* __restrict__ c, float* __restrict__ out)
{
    extern __shared__ float sAcl[];            // [TT][NS][AS] closed-loop matrices
    __shared__ __align__(16) float sF[NS][NA]; // [A B]
    __shared__ __align__(16) float sW[NS][WS]; // P * F
    __shared__ __align__(16) float sQ[NA][QS];
    __shared__ __align__(16) float sP[NS][PS];
    __shared__ __align__(16) float sK[NC][NS];
    __shared__ float sq[NA], sp[NS], skk[NC];
    __shared__ float sBias[TT][NS];
    __shared__ float sX[TT][NS];

    const int tid = threadIdx.x;

    for (int idx = tid; idx < NS * NA; idx += NTHR) {
        int i = idx / NA, j = idx % NA;
        sF[i][j] = (j < NS) ? A[i * NS + j] : B[i * NC + (j - NS)];
    }
    __syncthreads();

    // Register-cached F column for this thread's Phase-B row index
    const int ci  = tid % NA;        // Q row (Phase B), also q index
    const int jqB = tid / NA;        // Phase B column quad (0..5 for tid<144)
    float Fc[NS];
#pragma unroll
    for (int k = 0; k < NS; ++k) Fc[k] = sF[k][ci];

    const float4* C4 = (const float4*)C;
    float4 creg = make_float4(0.f, 0.f, 0.f, 0.f);
    float  cq   = 0.f;
    if (tid < 144) creg = C4[(TT - 1) * (NA * NA / 4) + ci * (NA / 4) + jqB];
    if (tid < NA)  cq   = c[(TT - 1) * NA + tid];

    // ---------------- Backward Riccati pass ----------------
#pragma unroll 1
    for (int t = TT - 1; t >= 0; --t) {
        if (t != TT - 1) {
            // Phase A: W = P * F   (96 threads, 1x4 strips)
            if (tid < 96) {
                int i = tid & 15, jq = tid >> 4;
                float4 s = make_float4(0.f, 0.f, 0.f, 0.f);
#pragma unroll
                for (int k = 0; k < NS; ++k) {
                    float p = sP[i][k];
                    float4 f = *(const float4*)&sF[k][4 * jq];
                    s.x = fmaf(p, f.x, s.x); s.y = fmaf(p, f.y, s.y);
                    s.z = fmaf(p, f.z, s.z); s.w = fmaf(p, f.w, s.w);
                }
                *(float4*)&sW[i][4 * jq] = s;
            }
            __syncthreads();
        }

        // Phase B: Q = C_t + F^T W ; q = c_t + F^T p
        if (tid < 144) {
            float4 s = creg;
            if (t != TT - 1) {
#pragma unroll
                for (int k = 0; k < NS; ++k) {
                    float f = Fc[k];
                    float4 w = *(const float4*)&sW[k][4 * jqB];
                    s.x = fmaf(f, w.x, s.x); s.y = fmaf(f, w.y, s.y);
                    s.z = fmaf(f, w.z, s.z); s.w = fmaf(f, w.w, s.w);
                }
            }
            *(float4*)&sQ[ci][4 * jqB] = s;
        }
        if (tid < NA) {
            float s = cq;
            if (t != TT - 1) {
#pragma unroll
                for (int k = 0; k < NS; ++k) s = fmaf(Fc[k], sp[k], s);
            }
            sq[tid] = s;
        }
        // Prefetch next stage's cost tile (hidden behind Cholesky/solves)
        if (t > 0) {
            if (tid < 144) creg = C4[(t - 1) * (NA * NA / 4) + ci * (NA / 4) + jqB];
            if (tid < NA)  cq   = c[(t - 1) * NA + tid];
        }
        __syncthreads();

        // Phase C+D: lanes 0..16 each build the 8x8 Cholesky in registers
        // (redundant per-thread -> no broadcast, no shared round-trip),
        // then solve their own RHS column. No divides: rsqrtf + reciprocal.
        if (tid <= NS) {
            float L[NC][NC];
            float invd[NC];
#pragma unroll
            for (int j = 0; j < NC; ++j) {
                float d = sQ[NS + j][NS + j];
#pragma unroll
                for (int k = 0; k < j; ++k) d = fmaf(-L[j][k], L[j][k], d);
                float r = rsqrtf(d);
                invd[j] = r;
#pragma unroll
                for (int i2 = j + 1; i2 < NC; ++i2) {
                    float s = sQ[NS + i2][NS + j];
#pragma unroll
                    for (int k = 0; k < j; ++k) s = fmaf(-L[i2][k], L[j][k], s);
                    L[i2][j] = s * r;
                }
            }
            float y[NC];
#pragma unroll
            for (int a = 0; a < NC; ++a)
                y[a] = (tid < NS) ? sQ[NS + a][tid] : sq[NS + a];
#pragma unroll
            for (int a = 0; a < NC; ++a) {              // L y' = y
                float s = y[a];
#pragma unroll
                for (int k = 0; k < a; ++k) s = fmaf(-L[a][k], y[k], s);
                y[a] = s * invd[a];
            }
#pragma unroll
            for (int a = NC - 1; a >= 0; --a) {         // L^T y'' = y'
                float s = y[a];
#pragma unroll
                for (int k = a + 1; k < NC; ++k) s = fmaf(-L[k][a], y[k], s);
                y[a] = s * invd[a];
            }
            if (tid < NS) {
#pragma unroll
                for (int a = 0; a < NC; ++a) { sK[a][tid] = y[a]; g_K[t][a][tid] = y[a]; }
            } else {
#pragma unroll
                for (int a = 0; a < NC; ++a) { skk[a] = y[a]; g_kk[t][a] = y[a]; }
            }
        }
        __syncthreads();

        // Phase E (all groups independent):
        if (tid < 64) {                 // P = Qxx - Qxu K
            int i = tid & 15, jq = tid >> 4;
            float4 s = *(const float4*)&sQ[i][4 * jq];
#pragma unroll
            for (int m = 0; m < NC; ++m) {
                float qm = sQ[i][NS + m];
                float4 kv = *(const float4*)&sK[m][4 * jq];
                s.x = fmaf(-qm, kv.x, s.x); s.y = fmaf(-qm, kv.y, s.y);
                s.z = fmaf(-qm, kv.z, s.z); s.w = fmaf(-qm, kv.w, s.w);
            }
            *(float4*)&sP[i][4 * jq] = s;
            *(float4*)&g_P[t][i][4 * jq] = s;
        } else if (tid < 80) {          // p = qx - Qxu kk
            int i = tid - 64;
            float s = sq[i];
#pragma unroll
            for (int m = 0; m < NC; ++m) s = fmaf(-sQ[i][NS + m], skk[m], s);
            sp[i] = s; g_p[t][i] = s;
        } else if (tid < 144) {         // Acl = A - B K
            int idx = tid - 80, i = idx & 15, jq = idx >> 4;
            float4 s = *(const float4*)&sF[i][4 * jq];
#pragma unroll
            for (int m = 0; m < NC; ++m) {
                float bm = sF[i][NS + m];
                float4 kv = *(const float4*)&sK[m][4 * jq];
                s.x = fmaf(-bm, kv.x, s.x); s.y = fmaf(-bm, kv.y, s.y);
                s.z = fmaf(-bm, kv.z, s.z); s.w = fmaf(-bm, kv.w, s.w);
            }
            float* ap = &sAcl[(t * NS + i) * AS + 4 * jq];
            ap[0] = s.x; ap[1] = s.y; ap[2] = s.z; ap[3] = s.w;
        } else {                        // bias = -B kk
            int i = tid - 144;
            float s = 0.f;
#pragma unroll
            for (int m = 0; m < NC; ++m) s = fmaf(-sF[i][NS + m], skk[m], s);
            sBias[t][i] = s;
        }
        __syncthreads();
    }

    // ---------------- Forward rollout: single warp, shuffle recurrence ----------------
    if (tid < 32) {
        int i = tid & 15;
        float x = (tid < NS) ? x0[tid] : 0.f;
#pragma unroll 1
        for (int t = 0; t < TT; ++t) {
            if (tid < NS) { out[t * NA + tid] = x; sX[t][tid] = x; }
            if (t < TT - 1) {
                float s = sBias[t][i];
                const float* ar = &sAcl[(t * NS + i) * AS];
#pragma unroll
                for (int k = 0; k < NS; ++k) {
                    float xk = __shfl_sync(0xffffffffu, x, k);
                    s = fmaf(ar[k], xk, s);
                }
                x = s;
            }
        }
    }
    __syncthreads();

    // ---------------- Parallel output post-pass ----------------
    // u_t = -(K_t x_t + kk_t)
    for (int idx = tid; idx < TT * NC; idx += NTHR) {
        int t = idx >> 3, m = idx & 7;
        float s = g_kk[t][m];
        const float4* Kr = (const float4*)&g_K[t][m][0];
        const float* xr = &sX[t][0];
#pragma unroll
        for (int q = 0; q < 4; ++q) {
            float4 v = Kr[q];
            s = fmaf(v.x, xr[4 * q + 0], s); s = fmaf(v.y, xr[4 * q + 1], s);
            s = fmaf(v.z, xr[4 * q + 2], s); s = fmaf(v.w, xr[4 * q + 3], s);
        }
        out[t * NA + NS + m] = -s;
    }
    // mu_t = P_t x_t + p_t  (negated at t=0)
    for (int idx = tid; idx < TT * NS; idx += NTHR) {
        int t = idx >> 4, i = idx & 15;
        float s = g_p[t][i];
        const float4* Pr = (const float4*)&g_P[t][i][0];
        const float* xr = &sX[t][0];
#pragma unroll
        for (int q = 0; q < 4; ++q) {
            float4 v = Pr[q];
            s = fmaf(v.x, xr[4 * q + 0], s); s = fmaf(v.y, xr[4 * q + 1], s);
            s = fmaf(v.z, xr[4 * q + 2], s); s = fmaf(v.w, xr[4 * q + 3], s);
        }
        out[TT * NA + idx] = (t == 0) ? -s : s;
    }
}

extern "C" void kernel_launch(void* const* d_in, const int* in_sizes, int n_in,
                              void* d_out, int out_size) {
    const float* A  = (const float*)d_in[0];
    const float* B  = (const float*)d_in[1];
    const float* x0 = (const float*)d_in[2];
    const float* C  = (const float*)d_in[3];
    const float* c  = (const float*)d_in[4];
    float* out = (float*)d_out;

    const int dyn = TT * NS * AS * sizeof(float);  // 139264 B
    // Sticky per-function attribute; first (non-captured) correctness call sets it.
    cudaFuncSetAttribute(lqr_kernel, cudaFuncAttributeMaxDynamicSharedMemorySize, dyn);
    lqr_kernel<<<1, NTHR, dyn>>>(A, B, x0, C, c, out);
}